// round 16
// baseline (speedup 1.0000x reference)
#include <cuda_runtime.h>

#define Bdim 256
#define Sdim 512
#define Fdim 64
#define Hdim 128
#define BS   (Bdim * Sdim)
#define NBLK 128           // 2 batch rows per block
#define KQ   28            // streamed Whh quad groups (k = 16..127)
#define NR   14            // register-resident q-groups of the streamed tail
#define CH1  (NR + 7)      // chunk split for warp-specialized overlap

__device__ float g_invDenom[Sdim];
__device__ float g_lossPartial[NBLK];
__device__ float g_WhhQ[KQ * 512 * 4];            // [(q*512+j)*4+r] = Whh[j][16+4q+r]
__device__ float g_gh[(size_t)BS * Hdim];         // gamma_h
__device__ float g_beta[(size_t)BS * Fdim];       // beta
__device__ float g_gml[(size_t)BS * 512];         // [b][s][j]: ml@WihMask^T + bio

typedef unsigned long long u64;
__device__ __forceinline__ void up2(u64 v, float& lo, float& hi) {
    unsigned a, b; asm("mov.b64 {%0,%1},%2;" : "=r"(a), "=r"(b) : "l"(v));
    lo = __uint_as_float(a); hi = __uint_as_float(b);
}
__device__ __forceinline__ u64 ff2(u64 a, u64 b, u64 c) {
    u64 d; asm("fma.rn.f32x2 %0,%1,%2,%3;" : "=l"(d) : "l"(a), "l"(b), "l"(c)); return d;
}
__device__ __forceinline__ float fsig(float v) {
    const float e = __expf(-v);
    return __fdividef(1.0f, 1.0f + e);
}
__device__ __forceinline__ float ftanh(float v) {
    const float vc = fminf(fmaxf(v, -15.0f), 15.0f);
    const float e = __expf(2.0f * vc);
    return __fdividef(e - 1.0f, e + 1.0f);
}

// ================= small pre kernel: denom + whhq only =================
__global__ __launch_bounds__(256) void rits_pre(
    const float* __restrict__ m, const float* __restrict__ Whh)
{
    __shared__ float red[256];
    const int b = blockIdx.x, t = threadIdx.x;
    if (b < 512) {
        const int s = b;
        const float4* p = (const float4*)(m + (size_t)t * Sdim * Fdim + (size_t)s * Fdim);
        float sum = 0.f;
#pragma unroll
        for (int i = 0; i < 16; ++i) { float4 v = p[i]; sum += v.x + v.y + v.z + v.w; }
        red[t] = sum;
        __syncthreads();
        for (int off = 128; off > 0; off >>= 1) { if (t < off) red[t] += red[t + off]; __syncthreads(); }
        if (t == 0) g_invDenom[s] = 1.0f / (red[0] + 1e-5f);
    } else {
        const int i = (b - 512) * 256 + t;
        if (i < KQ * 512 * 4) {
            const int r = i & 3, j = (i >> 2) & 511, q = i >> 11;
            g_WhhQ[i] = Whh[j * Hdim + 16 + 4 * q + r];
        }
    }
}

// ================= main kernel =================
// precompute smem layout (floats)
#define PW_DH  0
#define PB_DH  8192
#define PW_WC  8320
#define PD_WDM 16512
#define PB_DM  16576
#define PB_WC  16640
#define PW_IH  16704
#define PB_IO  49472
#define P_TL   49984
#define P_MB   50496
#define P_GM   51008
// main-loop layout
#define M_WIHQ 0
#define M_WHHR 32768
#define M_WTRQ 40960
#define M_WFRQ 49152
#define M_HR   53248
#define M_XC   53504
#define M_CLC  53632
#define M_GT   53760
#define M_BTR  54784
#define M_BFR  54848
#define M_RED  54912
#define M_SMF  55168
#define M_SMB  (M_SMF * 4)   // 220,672 B

#define FS2(WP0, WP1, AP, STR) do {                                     \
    const ulonglong2 w0_ = *(const ulonglong2*)(WP0);                   \
    const ulonglong2 w1_ = *(const ulonglong2*)(WP1);                   \
    { const ulonglong2 a_ = *(const ulonglong2*)(AP);                   \
      A00 = ff2(w0_.x, a_.x, A00); A00 = ff2(w0_.y, a_.y, A00);         \
      A10 = ff2(w1_.x, a_.x, A10); A10 = ff2(w1_.y, a_.y, A10); }       \
    { const ulonglong2 a_ = *(const ulonglong2*)((AP) + (STR));         \
      A01 = ff2(w0_.x, a_.x, A01); A01 = ff2(w0_.y, a_.y, A01);         \
      A11 = ff2(w1_.x, a_.x, A11); A11 = ff2(w1_.y, a_.y, A11); }       \
} while (0)

// streamed variant accumulating into S-regs
#define FS2S(WP0, WP1, AP, STR) do {                                    \
    const ulonglong2 w0_ = *(const ulonglong2*)(WP0);                   \
    const ulonglong2 w1_ = *(const ulonglong2*)(WP1);                   \
    { const ulonglong2 a_ = *(const ulonglong2*)(AP);                   \
      S00 = ff2(w0_.x, a_.x, S00); S00 = ff2(w0_.y, a_.y, S00);         \
      S10 = ff2(w1_.x, a_.x, S10); S10 = ff2(w1_.y, a_.y, S10); }       \
    { const ulonglong2 a_ = *(const ulonglong2*)((AP) + (STR));         \
      S01 = ff2(w0_.x, a_.x, S01); S01 = ff2(w0_.y, a_.y, S01);         \
      S11 = ff2(w1_.x, a_.x, S11); S11 = ff2(w1_.y, a_.y, S11); }       \
} while (0)

__global__ __launch_bounds__(256, 1) void rits_main(
    const float* __restrict__ x, const float* __restrict__ m, const float* __restrict__ tt,
    const float* __restrict__ Wdh, const float* __restrict__ bdh,
    const float* __restrict__ Wdm, const float* __restrict__ bdm,
    const float* __restrict__ Wtr, const float* __restrict__ btr,
    const float* __restrict__ Wfr, const float* __restrict__ bfr,
    const float* __restrict__ Wwc, const float* __restrict__ bwc,
    const float* __restrict__ Wih, const float* __restrict__ Whh,
    const float* __restrict__ bih, const float* __restrict__ bhh,
    float* __restrict__ out)
{
    extern __shared__ float sm[];
    const int t = threadIdx.x;
    const int b0 = blockIdx.x * 2;

    // ============== single-pass in-block precompute (gh + beta + gml) ==============
    {
        const int row = t >> 7, sP = (t >> 6) & 1, f = t & 63;
        const int hh = t & 127;
        const int j0p = t, j1p = t + 256;

        for (int i = t; i < 8192; i += 256) { const int r = i & 1, h2 = (i >> 1) & 127, k2 = i >> 8; sm[PW_DH + (k2 * 128 + h2) * 2 + r] = Wdh[h2 * 64 + 2 * k2 + r]; }
        if (t < 128) sm[PB_DH + t] = bdh[t];
        for (int i = t; i < 8192; i += 256) { const int r = i & 1, f2 = (i >> 1) & 63, k2 = i >> 7; sm[PW_WC + (k2 * 64 + f2) * 2 + r] = Wwc[f2 * 128 + 2 * k2 + r]; }
        if (t < 64) { sm[PD_WDM + t] = Wdm[t * 64 + t]; sm[PB_DM + t] = bdm[t]; sm[PB_WC + t] = bwc[t]; }
        for (int i = t; i < 32768; i += 256) { const int r = i & 1, j = (i >> 1) & 511, k2 = i >> 10; sm[PW_IH + (k2 * 512 + j) * 2 + r] = Wih[j * 128 + 64 + 2 * k2 + r]; }
        for (int i = t; i < 512; i += 256) sm[PB_IO + i] = bih[i] + bhh[i];

        float ptv = tt[((size_t)(b0 + row) * Sdim + sP) * 64 + f];
        float pmv = m[((size_t)(b0 + row) * Sdim + sP) * 64 + f];
        __syncthreads();

        for (int it = 0; it < 256; ++it) {
            const int s0 = 2 * it;
            const int buf = it & 1;
            float* TL = sm + P_TL + buf * 256;
            float* MB = sm + P_MB + buf * 256;
            float* GM = sm + P_GM + buf * 256;
            const float ctv = ptv;
            TL[(row * 2 + sP) * 64 + f] = ptv;
            MB[(row * 2 + sP) * 64 + f] = pmv;
            __syncthreads();
            if (it < 255) {
                ptv = tt[((size_t)(b0 + row) * Sdim + s0 + 2 + sP) * 64 + f];
                pmv = m[((size_t)(b0 + row) * Sdim + s0 + 2 + sP) * 64 + f];
            }
            GM[(row * 2 + sP) * 64 + f] = __expf(-fmaxf(ctv * sm[PD_WDM + f] + sm[PB_DM + f], 0.f));
            {
                u64 a0 = 0ULL, a1 = 0ULL;
                const float* x0 = TL + (row * 2) * 64;
                const float* x1 = x0 + 64;
#pragma unroll
                for (int k2 = 0; k2 < 32; ++k2) {
                    const u64 w = *(const u64*)(sm + PW_DH + (k2 * 128 + hh) * 2);
                    a0 = ff2(w, *(const u64*)(x0 + 2 * k2), a0);
                    a1 = ff2(w, *(const u64*)(x1 + 2 * k2), a1);
                }
                const float bb = sm[PB_DH + hh];
                float lo, hi;
                up2(a0, lo, hi);
                g_gh[((size_t)(b0 + row) * Sdim + s0) * 128 + hh] = __expf(-fmaxf(lo + hi + bb, 0.f));
                up2(a1, lo, hi);
                g_gh[((size_t)(b0 + row) * Sdim + s0 + 1) * 128 + hh] = __expf(-fmaxf(lo + hi + bb, 0.f));
            }
            __syncthreads();
            {
                u64 aA = 0ULL, aB = 0ULL;
                const float* gmp = GM + (row * 2 + sP) * 64;
                const float* mlp = MB + (row * 2 + sP) * 64;
#pragma unroll
                for (int k2 = 0; k2 < 32; ++k2) {
                    aA = ff2(*(const u64*)(sm + PW_WC + (k2 * 64 + f) * 2), *(const u64*)(gmp + 2 * k2), aA);
                    aB = ff2(*(const u64*)(sm + PW_WC + ((32 + k2) * 64 + f) * 2), *(const u64*)(mlp + 2 * k2), aB);
                }
                float lA, hA, lB, hB;
                up2(aA, lA, hA); up2(aB, lB, hB);
                g_beta[((size_t)(b0 + row) * Sdim + s0 + sP) * 64 + f] = (lA + hA) + (lB + hB) + sm[PB_WC + f];
            }
            {
                u64 a00 = 0ULL, a01 = 0ULL, a02 = 0ULL, a03 = 0ULL;
                u64 a10 = 0ULL, a11 = 0ULL, a12 = 0ULL, a13 = 0ULL;
#pragma unroll
                for (int k2 = 0; k2 < 32; ++k2) {
                    const u64 w0 = *(const u64*)(sm + PW_IH + (k2 * 512 + j0p) * 2);
                    const u64 w1 = *(const u64*)(sm + PW_IH + (k2 * 512 + j1p) * 2);
                    const u64 x00 = *(const u64*)(MB + 0 * 64 + 2 * k2);
                    const u64 x01 = *(const u64*)(MB + 1 * 64 + 2 * k2);
                    const u64 x10 = *(const u64*)(MB + 2 * 64 + 2 * k2);
                    const u64 x11 = *(const u64*)(MB + 3 * 64 + 2 * k2);
                    a00 = ff2(w0, x00, a00); a01 = ff2(w0, x01, a01);
                    a02 = ff2(w0, x10, a02); a03 = ff2(w0, x11, a03);
                    a10 = ff2(w1, x00, a10); a11 = ff2(w1, x01, a11);
                    a12 = ff2(w1, x10, a12); a13 = ff2(w1, x11, a13);
                }
                const float bj0 = sm[PB_IO + j0p], bj1 = sm[PB_IO + j1p];
                float lo, hi;
                up2(a00, lo, hi); g_gml[((size_t)(b0 + 0) * Sdim + s0) * 512 + j0p]     = lo + hi + bj0;
                up2(a01, lo, hi); g_gml[((size_t)(b0 + 0) * Sdim + s0 + 1) * 512 + j0p] = lo + hi + bj0;
                up2(a02, lo, hi); g_gml[((size_t)(b0 + 1) * Sdim + s0) * 512 + j0p]     = lo + hi + bj0;
                up2(a03, lo, hi); g_gml[((size_t)(b0 + 1) * Sdim + s0 + 1) * 512 + j0p] = lo + hi + bj0;
                up2(a10, lo, hi); g_gml[((size_t)(b0 + 0) * Sdim + s0) * 512 + j1p]     = lo + hi + bj1;
                up2(a11, lo, hi); g_gml[((size_t)(b0 + 0) * Sdim + s0 + 1) * 512 + j1p] = lo + hi + bj1;
                up2(a12, lo, hi); g_gml[((size_t)(b0 + 1) * Sdim + s0) * 512 + j1p]     = lo + hi + bj1;
                up2(a13, lo, hi); g_gml[((size_t)(b0 + 1) * Sdim + s0 + 1) * 512 + j1p] = lo + hi + bj1;
            }
        }
        __syncthreads();
    }

    // ================= load main-loop weight tiles =================
    for (int i = t; i < 32768; i += 256) { const int r = i & 3, j = (i >> 2) & 511, q = i >> 11; sm[M_WIHQ + i] = Wih[j * 128 + 4 * q + r]; }
    for (int i = t; i < 8192; i += 256)  { const int r = i & 3, j = (i >> 2) & 511, q = i >> 11; sm[M_WHHR + i] = Whh[j * 128 + 4 * q + r]; }
    for (int i = t; i < 8192; i += 256)  { const int r = i & 3, f = (i >> 2) & 63, q = i >> 8; sm[M_WTRQ + i] = Wtr[f * 128 + 4 * q + r]; }
    for (int i = t; i < 4096; i += 256)  { const int r = i & 3, f = (i >> 2) & 63, q = i >> 8; const int k = 4 * q + r; sm[M_WFRQ + i] = (k == f) ? 0.f : Wfr[f * 64 + k]; }
    if (t < 64) { sm[M_BTR + t] = btr[t]; sm[M_BFR + t] = bfr[t]; }
    sm[M_HR + t] = 0.f;
    float c_reg = 0.f, loss = 0.f;

    const int rE = t >> 6, fE = t & 63;
    const int j0 = t, j1 = t + 256;
    const int rG = t >> 7, jG = t & 127;
    const bool lowHalf = (t < 128);

    u64 rw[NR * 4];
#pragma unroll
    for (int q = 0; q < NR; ++q) {
        const ulonglong2 a = *(const ulonglong2*)(g_WhhQ + ((size_t)q * 512 + j0) * 4);
        const ulonglong2 bq = *(const ulonglong2*)(g_WhhQ + ((size_t)q * 512 + j1) * 4);
        rw[4 * q] = a.x; rw[4 * q + 1] = a.y; rw[4 * q + 2] = bq.x; rw[4 * q + 3] = bq.y;
    }

    float cx = 0.f, cm = 0.f, cbeta = 0.f;
    if (lowHalf) {
        const size_t idxP = ((size_t)(b0 + rE) * Sdim) * Fdim + fE;
        cx = x[idxP]; cm = m[idxP]; cbeta = g_beta[idxP];
    }
    float cgml[4];
    cgml[0] = g_gml[((size_t)(b0 + 0) * Sdim) * 512 + j0];
    cgml[1] = g_gml[((size_t)(b0 + 1) * Sdim) * 512 + j0];
    cgml[2] = g_gml[((size_t)(b0 + 0) * Sdim) * 512 + j1];
    cgml[3] = g_gml[((size_t)(b0 + 1) * Sdim) * 512 + j1];
    __syncthreads();

    for (int s = 0; s < Sdim; ++s) {
        const int sn = (s < Sdim - 1) ? s + 1 : s;
        const float ghv = g_gh[((size_t)(b0 + rG) * Sdim + sn) * Hdim + jG];
        float nx = 0.f, nm = 0.f, nbeta = 0.f, cInv = 0.f;
        if (lowHalf) {
            cInv = g_invDenom[s];
            const size_t idxN = ((size_t)(b0 + rE) * Sdim + sn) * Fdim + fE;
            nx = x[idxN]; nm = m[idxN]; nbeta = g_beta[idxN];
        }
        float ngml[4];
        ngml[0] = g_gml[((size_t)(b0 + 0) * Sdim + sn) * 512 + j0];
        ngml[1] = g_gml[((size_t)(b0 + 1) * Sdim + sn) * 512 + j0];
        ngml[2] = g_gml[((size_t)(b0 + 0) * Sdim + sn) * 512 + j1];
        ngml[3] = g_gml[((size_t)(b0 + 1) * Sdim + sn) * 512 + j1];

        u64 S00 = 0ULL, S01 = 0ULL, S10 = 0ULL, S11 = 0ULL;  // streamed partials (high half)

        // C: xl_hat (t<128)  |  streamed chunk1 (t>=128)
        float xh = 0.f;
        if (lowHalf) {
            u64 ac0 = 0ULL, ac1 = 0ULL, ac2 = 0ULL, ac3 = 0ULL;
            const float* hr = sm + M_HR + rE * 128;
#pragma unroll
            for (int q = 0; q < 32; q += 4) {
                { const ulonglong2 w = *(const ulonglong2*)(sm + M_WTRQ + (q * 64 + fE) * 4);
                  const ulonglong2 a = *(const ulonglong2*)(hr + 4 * q);
                  ac0 = ff2(w.x, a.x, ac0); ac0 = ff2(w.y, a.y, ac0); }
                { const ulonglong2 w = *(const ulonglong2*)(sm + M_WTRQ + ((q + 1) * 64 + fE) * 4);
                  const ulonglong2 a = *(const ulonglong2*)(hr + 4 * (q + 1));
                  ac1 = ff2(w.x, a.x, ac1); ac1 = ff2(w.y, a.y, ac1); }
                { const ulonglong2 w = *(const ulonglong2*)(sm + M_WTRQ + ((q + 2) * 64 + fE) * 4);
                  const ulonglong2 a = *(const ulonglong2*)(hr + 4 * (q + 2));
                  ac2 = ff2(w.x, a.x, ac2); ac2 = ff2(w.y, a.y, ac2); }
                { const ulonglong2 w = *(const ulonglong2*)(sm + M_WTRQ + ((q + 3) * 64 + fE) * 4);
                  const ulonglong2 a = *(const ulonglong2*)(hr + 4 * (q + 3));
                  ac3 = ff2(w.x, a.x, ac3); ac3 = ff2(w.y, a.y, ac3); }
            }
            float l0, h0, l1, h1, l2, h2, l3, h3;
            up2(ac0, l0, h0); up2(ac1, l1, h1); up2(ac2, l2, h2); up2(ac3, l3, h3);
            xh = sm[M_BTR + fE] + ((l0 + h0) + (l1 + h1)) + ((l2 + h2) + (l3 + h3));
            sm[M_XC + rE * 64 + fE] = cm * cx + (1.f - cm) * xh;
        } else {
#pragma unroll
            for (int q = NR; q < CH1; ++q)
                FS2S(g_WhhQ + ((size_t)q * 512 + j0) * 4,
                     g_WhhQ + ((size_t)q * 512 + j1) * 4,
                     sm + M_HR + 16 + 4 * q, 128);
        }
        __syncthreads();

        // D+E (t<128)  |  streamed chunk2 (t>=128)
        if (lowHalf) {
            u64 ac0 = 0ULL, ac1 = 0ULL;
            const float* xr = sm + M_XC + rE * 64;
#pragma unroll
            for (int q = 0; q < 16; q += 2) {
                { const ulonglong2 w = *(const ulonglong2*)(sm + M_WFRQ + (q * 64 + fE) * 4);
                  const ulonglong2 a = *(const ulonglong2*)(xr + 4 * q);
                  ac0 = ff2(w.x, a.x, ac0); ac0 = ff2(w.y, a.y, ac0); }
                { const ulonglong2 w = *(const ulonglong2*)(sm + M_WFRQ + ((q + 1) * 64 + fE) * 4);
                  const ulonglong2 a = *(const ulonglong2*)(xr + 4 * (q + 1));
                  ac1 = ff2(w.x, a.x, ac1); ac1 = ff2(w.y, a.y, ac1); }
            }
            float l0, h0, l1, h1;
            up2(ac0, l0, h0); up2(ac1, l1, h1);
            const float zh = sm[M_BFR + fE] + (l0 + h0) + (l1 + h1);
            const float ch = cbeta * zh + (1.f - cbeta) * xh;
            const float cc = cm * cx + (1.f - cm) * ch;
            sm[M_CLC + rE * 64 + fE] = cc;
            out[((size_t)(b0 + rE) * Sdim + s) * Fdim + fE] = cc;
            const float d1 = cx - xh, d2 = cx - zh, d3 = cx - ch;
            loss += cm * (d1 * d1 + d2 * d2 + d3 * d3) * cInv;
        } else {
#pragma unroll
            for (int q = CH1; q < KQ; ++q)
                FS2S(g_WhhQ + ((size_t)q * 512 + j0) * 4,
                     g_WhhQ + ((size_t)q * 512 + j1) * 4,
                     sm + M_HR + 16 + 4 * q, 128);
        }
        __syncthreads();

        // F: gates = gml + clc @ WihClc^T + h @ Whh^T
        {
            u64 A00 = S00, A01 = S01, A10 = S10, A11 = S11;
#pragma unroll
            for (int q = 0; q < 16; ++q)
                FS2(sm + M_WIHQ + (q * 512 + j0) * 4,
                    sm + M_WIHQ + (q * 512 + j1) * 4,
                    sm + M_CLC + 4 * q, 64);
#pragma unroll
            for (int q = 0; q < 4; ++q)
                FS2(sm + M_WHHR + (q * 512 + j0) * 4,
                    sm + M_WHHR + (q * 512 + j1) * 4,
                    sm + M_HR + 4 * q, 128);
#pragma unroll
            for (int q = 0; q < NR; ++q) {
                const float* AP = sm + M_HR + 16 + 4 * q;
                { const ulonglong2 a_ = *(const ulonglong2*)(AP);
                  A00 = ff2(rw[4 * q], a_.x, A00); A00 = ff2(rw[4 * q + 1], a_.y, A00);
                  A10 = ff2(rw[4 * q + 2], a_.x, A10); A10 = ff2(rw[4 * q + 3], a_.y, A10); }
                { const ulonglong2 a_ = *(const ulonglong2*)(AP + 128);
                  A01 = ff2(rw[4 * q], a_.x, A01); A01 = ff2(rw[4 * q + 1], a_.y, A01);
                  A11 = ff2(rw[4 * q + 2], a_.x, A11); A11 = ff2(rw[4 * q + 3], a_.y, A11); }
            }
            if (lowHalf) {
#pragma unroll
                for (int q = NR; q < KQ; ++q)
                    FS2(g_WhhQ + ((size_t)q * 512 + j0) * 4,
                        g_WhhQ + ((size_t)q * 512 + j1) * 4,
                        sm + M_HR + 16 + 4 * q, 128);
            }
            float lo, hi;
            up2(A00, lo, hi); sm[M_GT + 0 * 512 + j0] = lo + hi + cgml[0];
            up2(A01, lo, hi); sm[M_GT + 1 * 512 + j0] = lo + hi + cgml[1];
            up2(A10, lo, hi); sm[M_GT + 0 * 512 + j1] = lo + hi + cgml[2];
            up2(A11, lo, hi); sm[M_GT + 1 * 512 + j1] = lo + hi + cgml[3];
        }
        __syncthreads();

        // G: LSTM update + apply gamma_h(s+1)
        {
            const float* gg = sm + M_GT + rG * 512;
            const float iv = fsig(gg[jG]);
            const float fv = fsig(gg[128 + jG]);
            const float gv = ftanh(gg[256 + jG]);
            const float ov = fsig(gg[384 + jG]);
            c_reg = fv * c_reg + iv * gv;
            sm[M_HR + rG * 128 + jG] = ov * ftanh(c_reg) * ghv;
        }
        __syncthreads();

        cx = nx; cm = nm; cbeta = nbeta;
#pragma unroll
        for (int r = 0; r < 4; ++r) cgml[r] = ngml[r];
    }

    sm[M_RED + t] = loss;
    __syncthreads();
    for (int off = 128; off > 0; off >>= 1) { if (t < off) sm[M_RED + t] += sm[M_RED + t + off]; __syncthreads(); }
    if (t == 0) g_lossPartial[blockIdx.x] = sm[M_RED];
}

__global__ void rits_loss_final(float* __restrict__ out, int out_size) {
    __shared__ float red[NBLK];
    const int t = threadIdx.x;
    red[t] = g_lossPartial[t];
    __syncthreads();
    for (int off = NBLK / 2; off > 0; off >>= 1) { if (t < off) red[t] += red[t + off]; __syncthreads(); }
    const long long bsf = (long long)Bdim * Sdim * Fdim;
    if (t == 0 && (long long)out_size > bsf) out[bsf] = red[0] / (float)Sdim;
}

extern "C" void kernel_launch(void* const* d_in, const int* in_sizes, int n_in,
                              void* d_out, int out_size) {
    const float* x   = (const float*)d_in[0];
    const float* m   = (const float*)d_in[1];
    const float* tt  = (const float*)d_in[2];
    const float* Wdh = (const float*)d_in[3];
    const float* bdh = (const float*)d_in[4];
    const float* Wdm = (const float*)d_in[5];
    const float* bdm = (const float*)d_in[6];
    const float* Wtr = (const float*)d_in[7];
    const float* btr = (const float*)d_in[8];
    const float* Wfr = (const float*)d_in[9];
    const float* bfr = (const float*)d_in[10];
    const float* Wwc = (const float*)d_in[11];
    const float* bwc = (const float*)d_in[12];
    const float* Wih = (const float*)d_in[13];
    const float* Whh = (const float*)d_in[14];
    const float* bih = (const float*)d_in[15];
    const float* bhh = (const float*)d_in[16];
    float* out = (float*)d_out;

    cudaFuncSetAttribute(rits_main, cudaFuncAttributeMaxDynamicSharedMemorySize, M_SMB);

    rits_pre<<<736, 256>>>(m, Whh);
    rits_main<<<NBLK, 256, M_SMB>>>(x, m, tt, Wdh, bdh, Wdm, bdm, Wtr, btr,
                                    Wfr, bfr, Wwc, bwc, Wih, Whh, bih, bhh, out);
    rits_loss_final<<<1, NBLK>>>(out, out_size);
}